// round 14
// baseline (speedup 1.0000x reference)
#include <cuda_runtime.h>
#include <cuda_fp16.h>
#include <cuda_bf16.h>
#include <math.h>
#include <stdint.h>

// Problem constants
#define BATCH 32
#define SEQ   2048
#define HID   1024
#define KDIM  3072          // 3*HID
#define MROWS (BATCH*SEQ)   // 65536
#define NCHUNK 2                               // M-chunks for cvt/norm overlap
#define MB_PER_CHUNK (MROWS / 128 / NCHUNK)    // 256 m-blocks per chunk

// Scratch (device globals: allocation-free rule)
__device__ float  g_w[BATCH * SEQ];            // softmax weights
__device__ float  g_pp[8][BATCH * KDIM];       // pooled-trg partials (8 L-splits)
__device__ float  g_p[BATCH * KDIM];           // reduced pooled trg
__device__ float  g_np[8][MROWS];              // per-n-tile rowsq partials
__device__ __half g_trgh[(size_t)MROWS * KDIM];// fp16 trg (403 MB)
__device__ __half g_wh[(size_t)HID * KDIM];    // fp16 W   (6 MB)

// ---------------------------------------------------------------------------
// helpers
// ---------------------------------------------------------------------------
__device__ __forceinline__ uint32_t smem_u32(const void* p) {
    uint32_t a;
    asm("{ .reg .u64 t; cvta.to.shared.u64 t, %1; cvt.u32.u64 %0, t; }"
        : "=r"(a) : "l"(p));
    return a;
}

__device__ __forceinline__ void cp16(uint32_t saddr, const void* gaddr) {
    asm volatile("cp.async.cg.shared.global [%0], [%1], 16;"
                 :: "r"(saddr), "l"(gaddr) : "memory");
}

__device__ __forceinline__ void ldsm_x4(uint32_t& r0, uint32_t& r1,
                                        uint32_t& r2, uint32_t& r3, uint32_t addr) {
    asm volatile("ldmatrix.sync.aligned.m8n8.x4.shared.b16 {%0,%1,%2,%3}, [%4];"
                 : "=r"(r0), "=r"(r1), "=r"(r2), "=r"(r3) : "r"(addr));
}

__device__ __forceinline__ void mma_f16(float& d0, float& d1, float& d2, float& d3,
                                        uint32_t a0, uint32_t a1, uint32_t a2, uint32_t a3,
                                        uint32_t b0, uint32_t b1) {
    asm volatile(
        "mma.sync.aligned.m16n8k16.row.col.f32.f16.f16.f32 "
        "{%0,%1,%2,%3}, {%4,%5,%6,%7}, {%8,%9}, {%0,%1,%2,%3};"
        : "+f"(d0), "+f"(d1), "+f"(d2), "+f"(d3)
        : "r"(a0), "r"(a1), "r"(a2), "r"(a3), "r"(b0), "r"(b1));
}

// ---------------------------------------------------------------------------
// Kernel 0: fp32 -> fp16 conversion, 8 elements/thread
// ---------------------------------------------------------------------------
__global__ __launch_bounds__(256)
void k_cvt8(const float* __restrict__ in, __half* __restrict__ out)
{
    const size_t i = ((size_t)blockIdx.x * 256 + threadIdx.x) * 8;
    float4 v0 = *(const float4*)(in + i);
    float4 v1 = *(const float4*)(in + i + 4);
    __half2 h0 = __floats2half2_rn(v0.x, v0.y);
    __half2 h1 = __floats2half2_rn(v0.z, v0.w);
    __half2 h2 = __floats2half2_rn(v1.x, v1.y);
    __half2 h3 = __floats2half2_rn(v1.z, v1.w);
    uint4 u;
    u.x = *(uint32_t*)&h0; u.y = *(uint32_t*)&h1;
    u.z = *(uint32_t*)&h2; u.w = *(uint32_t*)&h3;
    *(uint4*)(out + i) = u;
}

// ---------------------------------------------------------------------------
// Kernel 1: partial rowsq for one 128x128 output tile, full K.
// fp16 mma.sync m16n8k16 + ldmatrix.x4, BK=64 halves, XOR-swizzled smem,
// double-buffered cp.async, 2 CTAs/SM. Chunked over M (2 chunks of 2048 CTAs
// = 7 waves each, same 14-wave total as unchunked) so trg conversion of
// chunk 1 overlaps chunk 0's compute.
// 256 threads = 8 warps, warp grid 4(M) x 2(N), warp tile 32x64.
// ---------------------------------------------------------------------------
#define BKH    64                              // k-halves per stage
#define TILE_B (128 * 128)                     // bytes per tile buffer (16 KB)
#define SMEM_NORM (4 * TILE_B)                 // A0,A1,B0,B1 -> 64 KB
#define NSTG   (KDIM / BKH)                    // 48

__global__ __launch_bounds__(256, 2)
void k_norm_h(const float* __restrict__ bias, int mb0)
{
    extern __shared__ __align__(128) char smem[];
    const uint32_t sb = smem_u32(smem);
    const uint32_t sA[2] = { sb,            sb + TILE_B };
    const uint32_t sB[2] = { sb + 2*TILE_B, sb + 3*TILE_B };

    __shared__ float rowsq_s[128][2];

    const int tid  = threadIdx.x;
    const int lane = tid & 31;
    const int w    = tid >> 5;
    const int wy   = w >> 1;                  // 0..3  (M)
    const int wx   = w & 1;                   // 0..1  (N)
    const int g    = lane >> 2;               // 0..7
    const int tig  = lane & 3;                // 0..3
    const int WM   = wy * 32;
    const int WN   = wx * 64;
    const int    nx = blockIdx.x;             // n-tile 0..7
    const int    n0 = nx * 128;
    const size_t m0 = (size_t)(mb0 + blockIdx.y) * 128;

    // ---- cp.async indexing: 1024 16B-chunks per tile, 4 per thread ----
    const int lrow[4] = { (tid + 0*256) >> 3, (tid + 1*256) >> 3,
                          (tid + 2*256) >> 3, (tid + 3*256) >> 3 };
    const int lc     = tid & 7;
    const int lcol8  = lc * 8;
    int soff[4];
    #pragma unroll
    for (int i = 0; i < 4; ++i)
        soff[i] = lrow[i] * 128 + ((lc ^ (lrow[i] & 7)) << 4);

    const __half* gA = g_trgh + m0 * (size_t)KDIM;
    const __half* gB = g_wh + (size_t)n0 * KDIM;

    // ---- ldmatrix per-lane row bases ----
    const int sub  = ((lane >> 3) & 1) * 8 + (lane & 7);
    const int hi   = (lane >> 4) & 1;
    const int mod7 = lane & 7;
    int aoff[2], boff[4];
    #pragma unroll
    for (int mt = 0; mt < 2; ++mt) aoff[mt] = (WM + mt*16 + sub) * 128;
    #pragma unroll
    for (int j = 0; j < 4; ++j)    boff[j]  = (WN + j*16  + sub) * 128;

    float acc[2][8][4];
    #pragma unroll
    for (int mt = 0; mt < 2; ++mt)
        #pragma unroll
        for (int nt = 0; nt < 8; ++nt)
            #pragma unroll
            for (int c = 0; c < 4; ++c) acc[mt][nt][c] = 0.f;

    // prologue: stage 0
    #pragma unroll
    for (int i = 0; i < 4; ++i) {
        cp16(sA[0] + soff[i], gA + (size_t)lrow[i] * KDIM + lcol8);
        cp16(sB[0] + soff[i], gB + (size_t)lrow[i] * KDIM + lcol8);
    }
    asm volatile("cp.async.commit_group;" ::: "memory");

    for (int s = 0; s < NSTG; ++s) {
        const int buf = s & 1;
        if (s + 1 < NSTG) {
            const int nb = buf ^ 1;
            const int k1 = (s + 1) * BKH;
            #pragma unroll
            for (int i = 0; i < 4; ++i) {
                cp16(sA[nb] + soff[i], gA + (size_t)lrow[i] * KDIM + k1 + lcol8);
                cp16(sB[nb] + soff[i], gB + (size_t)lrow[i] * KDIM + k1 + lcol8);
            }
            asm volatile("cp.async.commit_group;" ::: "memory");
            asm volatile("cp.async.wait_group 1;" ::: "memory");
        } else {
            asm volatile("cp.async.wait_group 0;" ::: "memory");
        }
        __syncthreads();

        const uint32_t bA = sA[buf];
        const uint32_t bB = sB[buf];
        #pragma unroll
        for (int ks = 0; ks < BKH / 16; ++ks) {
            const uint32_t sw = (uint32_t)(((ks*2 + hi) ^ mod7) << 4);
            uint32_t af[2][4], bf[8][2];
            #pragma unroll
            for (int mt = 0; mt < 2; ++mt)
                ldsm_x4(af[mt][0], af[mt][1], af[mt][2], af[mt][3],
                        bA + aoff[mt] + sw);
            #pragma unroll
            for (int j = 0; j < 4; ++j)
                ldsm_x4(bf[2*j][0], bf[2*j+1][0], bf[2*j][1], bf[2*j+1][1],
                        bB + boff[j] + sw);
            #pragma unroll
            for (int mt = 0; mt < 2; ++mt)
                #pragma unroll
                for (int nt = 0; nt < 8; ++nt)
                    mma_f16(acc[mt][nt][0], acc[mt][nt][1],
                            acc[mt][nt][2], acc[mt][nt][3],
                            af[mt][0], af[mt][1], af[mt][2], af[mt][3],
                            bf[nt][0], bf[nt][1]);
        }
        __syncthreads();
    }

    // epilogue: +bias, square-accumulate per row (partial over this n-tile)
    float rowsq[4] = {0.f, 0.f, 0.f, 0.f};
    #pragma unroll
    for (int nt = 0; nt < 8; ++nt) {
        const int cb = n0 + WN + nt*8 + 2*tig;
        const float b0 = __ldg(bias + cb);
        const float b1 = __ldg(bias + cb + 1);
        #pragma unroll
        for (int mt = 0; mt < 2; ++mt) {
            float v0 = acc[mt][nt][0] + b0;
            float v1 = acc[mt][nt][1] + b1;
            float v2 = acc[mt][nt][2] + b0;
            float v3 = acc[mt][nt][3] + b1;
            rowsq[mt*2+0] = fmaf(v0, v0, rowsq[mt*2+0]);
            rowsq[mt*2+0] = fmaf(v1, v1, rowsq[mt*2+0]);
            rowsq[mt*2+1] = fmaf(v2, v2, rowsq[mt*2+1]);
            rowsq[mt*2+1] = fmaf(v3, v3, rowsq[mt*2+1]);
        }
    }
    #pragma unroll
    for (int i = 0; i < 4; ++i) {
        rowsq[i] += __shfl_xor_sync(0xffffffffu, rowsq[i], 1);
        rowsq[i] += __shfl_xor_sync(0xffffffffu, rowsq[i], 2);
    }
    if (tig == 0) {
        #pragma unroll
        for (int mt = 0; mt < 2; ++mt)
            #pragma unroll
            for (int i = 0; i < 2; ++i)
                rowsq_s[WM + mt*16 + i*8 + g][wx] = rowsq[mt*2 + i];
    }
    __syncthreads();
    if (tid < 128)
        g_np[nx][m0 + tid] = rowsq_s[tid][0] + rowsq_s[tid][1];
}

// ---------------------------------------------------------------------------
// Kernel 2: combine rowsq partials -> norm1, then softmax over L -> g_w
// ---------------------------------------------------------------------------
__global__ void k_softmax(float* __restrict__ norm1)
{
    const int b = blockIdx.x;
    const int tid = threadIdx.x;
    __shared__ float red[256];

    for (int l = tid; l < SEQ; l += 256) {
        const int m = b * SEQ + l;
        float s = 0.f;
        #pragma unroll
        for (int j = 0; j < 8; ++j) s += g_np[j][m];
        norm1[m] = sqrtf(s);
    }
    __syncthreads();

    const float* x = norm1 + b * SEQ;
    float m = -1e30f;
    for (int l = tid; l < SEQ; l += 256) m = fmaxf(m, x[l]);
    red[tid] = m; __syncthreads();
    for (int s = 128; s > 0; s >>= 1) {
        if (tid < s) red[tid] = fmaxf(red[tid], red[tid + s]);
        __syncthreads();
    }
    float bm = red[0];
    __syncthreads();

    float sum = 0.0f;
    for (int l = tid; l < SEQ; l += 256) {
        float e = __expf(x[l] - bm);
        g_w[b * SEQ + l] = e;
        sum += e;
    }
    red[tid] = sum; __syncthreads();
    for (int s = 128; s > 0; s >>= 1) {
        if (tid < s) red[tid] += red[tid + s];
        __syncthreads();
    }
    float inv = 1.0f / red[0];
    for (int l = tid; l < SEQ; l += 256) g_w[b * SEQ + l] *= inv;
}

// ---------------------------------------------------------------------------
// Kernel 3: pooled partials from fp16 trg: g_pp[ls][b,k] = sum w[b,l]*trg[b,l,k]
// ---------------------------------------------------------------------------
__global__ void k_pool(void)
{
    const int kc = blockIdx.x;            // 0..2
    const int ls = blockIdx.y;            // 0..7
    const int b  = blockIdx.z;            // 0..31
    const int tid = threadIdx.x;
    const int k0 = kc * 1024 + tid * 4;

    const __half* base = g_trgh + (size_t)b * SEQ * KDIM;
    float4 acc = make_float4(0.f, 0.f, 0.f, 0.f);

    const int l0 = ls * 256;
    #pragma unroll 4
    for (int l = l0; l < l0 + 256; ++l) {
        float wl = g_w[b * SEQ + l];
        uint2 raw = *(const uint2*)(base + (size_t)l * KDIM + k0);
        float2 f0 = __half22float2(*(__half2*)&raw.x);
        float2 f1 = __half22float2(*(__half2*)&raw.y);
        acc.x = fmaf(wl, f0.x, acc.x);
        acc.y = fmaf(wl, f0.y, acc.y);
        acc.z = fmaf(wl, f1.x, acc.z);
        acc.w = fmaf(wl, f1.y, acc.w);
    }
    *(float4*)(&g_pp[ls][b * KDIM + k0]) = acc;
}

// ---------------------------------------------------------------------------
// Kernel 3b: reduce the 8 pooled partials -> g_p
// ---------------------------------------------------------------------------
__global__ __launch_bounds__(256)
void k_red(void)
{
    const int i = blockIdx.x * 256 + threadIdx.x;   // 0 .. BATCH*KDIM-1
    float s = 0.f;
    #pragma unroll
    for (int l = 0; l < 8; ++l) s += g_pp[l][i];
    g_p[i] = s;
}

// ---------------------------------------------------------------------------
// Kernel 4: summ[b,h] = g_p[b,:] . W[h,:] + bias[h]   (fp16 W, fp32 accum)
// ---------------------------------------------------------------------------
__global__ void k_out(const float* __restrict__ bias, float* __restrict__ summ)
{
    const int b = blockIdx.y;
    const int tid = threadIdx.x;
    const int lane = tid & 31;
    const int wid = tid >> 5;

    __shared__ float ps[KDIM];
    for (int k = tid; k < KDIM; k += 256)
        ps[k] = g_p[b * KDIM + k];
    __syncthreads();

    const int h = blockIdx.x * 8 + wid;
    const __half* wr = g_wh + (size_t)h * KDIM;
    float s = 0.0f;
    for (int k = lane * 8; k < KDIM; k += 256) {
        uint4 u = *(const uint4*)(wr + k);
        float2 w0 = __half22float2(*(__half2*)&u.x);
        float2 w1 = __half22float2(*(__half2*)&u.y);
        float2 w2 = __half22float2(*(__half2*)&u.z);
        float2 w3 = __half22float2(*(__half2*)&u.w);
        float4 p0 = *(const float4*)(ps + k);
        float4 p1 = *(const float4*)(ps + k + 4);
        s = fmaf(w0.x, p0.x, s); s = fmaf(w0.y, p0.y, s);
        s = fmaf(w1.x, p0.z, s); s = fmaf(w1.y, p0.w, s);
        s = fmaf(w2.x, p1.x, s); s = fmaf(w2.y, p1.y, s);
        s = fmaf(w3.x, p1.z, s); s = fmaf(w3.y, p1.w, s);
    }
    #pragma unroll
    for (int o = 16; o > 0; o >>= 1) s += __shfl_xor_sync(0xffffffffu, s, o);
    if (lane == 0) summ[b * HID + h] = s + bias[h];
}

// ---------------------------------------------------------------------------
extern "C" void kernel_launch(void* const* d_in, const int* in_sizes, int n_in,
                              void* d_out, int out_size)
{
    const float* trg  = (const float*)d_in[0];
    // d_in[1] = src (unused, n_layers == 0)
    const float* W    = (const float*)d_in[2];
    const float* bias = (const float*)d_in[3];

    float* out   = (float*)d_out;
    float* summ  = out;                   // [32, 1024]
    float* norm1 = out + BATCH * HID;     // [32, 2048]

    __half* trgh; cudaGetSymbolAddress((void**)&trgh, g_trgh);
    __half* wh;   cudaGetSymbolAddress((void**)&wh,   g_wh);

    cudaFuncSetAttribute(k_norm_h, cudaFuncAttributeMaxDynamicSharedMemorySize, SMEM_NORM);

    // Fork a side stream so trg conversion (HBM-bound) overlaps k_norm chunk 0
    // (tensor-bound). 2 chunks of 2048 CTAs = 7 waves each = same 14-wave
    // total as a single launch, so no wave-quantization loss (the R13 4-chunk
    // version paid 2 extra waves). Handles intentionally not destroyed
    // (correctness run + capture only).
    cudaStream_t s2;
    cudaStreamCreate(&s2);
    cudaEvent_t evFork, ev[NCHUNK];
    cudaEventCreateWithFlags(&evFork, cudaEventDisableTiming);
    for (int c = 0; c < NCHUNK; ++c)
        cudaEventCreateWithFlags(&ev[c], cudaEventDisableTiming);

    cudaEventRecord(evFork, 0);
    cudaStreamWaitEvent(s2, evFork, 0);

    const size_t chunk_elems = (size_t)MROWS * KDIM / NCHUNK;
    for (int c = 0; c < NCHUNK; ++c) {
        k_cvt8<<<(unsigned)(chunk_elems / (256 * 8)), 256, 0, s2>>>(
            trg + c * chunk_elems, trgh + c * chunk_elems);
        cudaEventRecord(ev[c], s2);
    }

    // main stream: W conversion runs concurrently with cvt(c0)
    k_cvt8<<<(HID * KDIM) / (256 * 8), 256>>>(W, wh);

    for (int c = 0; c < NCHUNK; ++c) {
        cudaStreamWaitEvent(0, ev[c], 0);   // joins s2 into capture at c=1
        k_norm_h<<<dim3(8, MB_PER_CHUNK), 256, SMEM_NORM>>>(bias, c * MB_PER_CHUNK);
    }

    k_softmax<<<BATCH, 256>>>(norm1);
    k_pool<<<dim3(3, 8, BATCH), 256>>>();
    k_red<<<(BATCH * KDIM) / 256, 256>>>();
    k_out<<<dim3(HID / 8, BATCH), 256>>>(bias, summ);
}

// round 15
// speedup vs baseline: 1.0356x; 1.0356x over previous
#include <cuda_runtime.h>
#include <cuda_fp16.h>
#include <cuda_bf16.h>
#include <math.h>
#include <stdint.h>

// Problem constants
#define BATCH 32
#define SEQ   2048
#define HID   1024
#define KDIM  3072          // 3*HID
#define MROWS (BATCH*SEQ)   // 65536

// Scratch (device globals: allocation-free rule)
__device__ float  g_w[BATCH * SEQ];            // softmax weights
__device__ float  g_pp[8][BATCH * KDIM];       // pooled-trg partials (8 L-splits)
__device__ float  g_p[BATCH * KDIM];           // reduced pooled trg
__device__ float  g_np[8][MROWS];              // per-n-tile rowsq partials
__device__ __half g_trgh[(size_t)MROWS * KDIM];// fp16 trg (403 MB)
__device__ __half g_wh[(size_t)HID * KDIM];    // fp16 W   (6 MB)

// ---------------------------------------------------------------------------
// helpers
// ---------------------------------------------------------------------------
__device__ __forceinline__ uint32_t smem_u32(const void* p) {
    uint32_t a;
    asm("{ .reg .u64 t; cvta.to.shared.u64 t, %1; cvt.u32.u64 %0, t; }"
        : "=r"(a) : "l"(p));
    return a;
}

__device__ __forceinline__ void cp16(uint32_t saddr, const void* gaddr) {
    asm volatile("cp.async.cg.shared.global [%0], [%1], 16;"
                 :: "r"(saddr), "l"(gaddr) : "memory");
}

__device__ __forceinline__ void ldsm_x4(uint32_t& r0, uint32_t& r1,
                                        uint32_t& r2, uint32_t& r3, uint32_t addr) {
    asm volatile("ldmatrix.sync.aligned.m8n8.x4.shared.b16 {%0,%1,%2,%3}, [%4];"
                 : "=r"(r0), "=r"(r1), "=r"(r2), "=r"(r3) : "r"(addr));
}

__device__ __forceinline__ void mma_f16(float& d0, float& d1, float& d2, float& d3,
                                        uint32_t a0, uint32_t a1, uint32_t a2, uint32_t a3,
                                        uint32_t b0, uint32_t b1) {
    asm volatile(
        "mma.sync.aligned.m16n8k16.row.col.f32.f16.f16.f32 "
        "{%0,%1,%2,%3}, {%4,%5,%6,%7}, {%8,%9}, {%0,%1,%2,%3};"
        : "+f"(d0), "+f"(d1), "+f"(d2), "+f"(d3)
        : "r"(a0), "r"(a1), "r"(a2), "r"(a3), "r"(b0), "r"(b1));
}

// ---------------------------------------------------------------------------
// Kernel 0: fp32 -> fp16 conversion, 8 elements/thread
// ---------------------------------------------------------------------------
__global__ __launch_bounds__(256)
void k_cvt8(const float* __restrict__ in, __half* __restrict__ out)
{
    const size_t i = ((size_t)blockIdx.x * 256 + threadIdx.x) * 8;
    float4 v0 = *(const float4*)(in + i);
    float4 v1 = *(const float4*)(in + i + 4);
    __half2 h0 = __floats2half2_rn(v0.x, v0.y);
    __half2 h1 = __floats2half2_rn(v0.z, v0.w);
    __half2 h2 = __floats2half2_rn(v1.x, v1.y);
    __half2 h3 = __floats2half2_rn(v1.z, v1.w);
    uint4 u;
    u.x = *(uint32_t*)&h0; u.y = *(uint32_t*)&h1;
    u.z = *(uint32_t*)&h2; u.w = *(uint32_t*)&h3;
    *(uint4*)(out + i) = u;
}

// ---------------------------------------------------------------------------
// Kernel 1: partial rowsq for one 128x128 output tile, full K.
// fp16 mma.sync m16n8k16 + ldmatrix.x4, BK=64 halves, XOR-swizzled smem,
// double-buffered cp.async, 2 CTAs/SM, single unchunked 4096-CTA launch
// (stream overlap is counterproductive: norm's 2 CTAs consume the full RF,
// so concurrent kernels just interleave and fragment waves — measured R13/14).
// 256 threads = 8 warps, warp grid 4(M) x 2(N), warp tile 32x64.
// ---------------------------------------------------------------------------
#define BKH    64                              // k-halves per stage
#define TILE_B (128 * 128)                     // bytes per tile buffer (16 KB)
#define SMEM_NORM (4 * TILE_B)                 // A0,A1,B0,B1 -> 64 KB
#define NSTG   (KDIM / BKH)                    // 48

__global__ __launch_bounds__(256, 2)
void k_norm_h(const float* __restrict__ bias)
{
    extern __shared__ __align__(128) char smem[];
    const uint32_t sb = smem_u32(smem);
    const uint32_t sA[2] = { sb,            sb + TILE_B };
    const uint32_t sB[2] = { sb + 2*TILE_B, sb + 3*TILE_B };

    __shared__ float rowsq_s[128][2];

    const int tid  = threadIdx.x;
    const int lane = tid & 31;
    const int w    = tid >> 5;
    const int wy   = w >> 1;                  // 0..3  (M)
    const int wx   = w & 1;                   // 0..1  (N)
    const int g    = lane >> 2;               // 0..7
    const int tig  = lane & 3;                // 0..3
    const int WM   = wy * 32;
    const int WN   = wx * 64;
    const int    nx = blockIdx.x;             // n-tile 0..7
    const int    n0 = nx * 128;
    const size_t m0 = (size_t)blockIdx.y * 128;

    // ---- cp.async indexing: 1024 16B-chunks per tile, 4 per thread ----
    const int lrow[4] = { (tid + 0*256) >> 3, (tid + 1*256) >> 3,
                          (tid + 2*256) >> 3, (tid + 3*256) >> 3 };
    const int lc     = tid & 7;
    const int lcol8  = lc * 8;
    int soff[4];
    #pragma unroll
    for (int i = 0; i < 4; ++i)
        soff[i] = lrow[i] * 128 + ((lc ^ (lrow[i] & 7)) << 4);

    const __half* gA = g_trgh + m0 * (size_t)KDIM;
    const __half* gB = g_wh + (size_t)n0 * KDIM;

    // ---- ldmatrix per-lane row bases ----
    const int sub  = ((lane >> 3) & 1) * 8 + (lane & 7);
    const int hi   = (lane >> 4) & 1;
    const int mod7 = lane & 7;
    int aoff[2], boff[4];
    #pragma unroll
    for (int mt = 0; mt < 2; ++mt) aoff[mt] = (WM + mt*16 + sub) * 128;
    #pragma unroll
    for (int j = 0; j < 4; ++j)    boff[j]  = (WN + j*16  + sub) * 128;

    float acc[2][8][4];
    #pragma unroll
    for (int mt = 0; mt < 2; ++mt)
        #pragma unroll
        for (int nt = 0; nt < 8; ++nt)
            #pragma unroll
            for (int c = 0; c < 4; ++c) acc[mt][nt][c] = 0.f;

    // prologue: stage 0
    #pragma unroll
    for (int i = 0; i < 4; ++i) {
        cp16(sA[0] + soff[i], gA + (size_t)lrow[i] * KDIM + lcol8);
        cp16(sB[0] + soff[i], gB + (size_t)lrow[i] * KDIM + lcol8);
    }
    asm volatile("cp.async.commit_group;" ::: "memory");

    for (int s = 0; s < NSTG; ++s) {
        const int buf = s & 1;
        if (s + 1 < NSTG) {
            const int nb = buf ^ 1;
            const int k1 = (s + 1) * BKH;
            #pragma unroll
            for (int i = 0; i < 4; ++i) {
                cp16(sA[nb] + soff[i], gA + (size_t)lrow[i] * KDIM + k1 + lcol8);
                cp16(sB[nb] + soff[i], gB + (size_t)lrow[i] * KDIM + k1 + lcol8);
            }
            asm volatile("cp.async.commit_group;" ::: "memory");
            asm volatile("cp.async.wait_group 1;" ::: "memory");
        } else {
            asm volatile("cp.async.wait_group 0;" ::: "memory");
        }
        __syncthreads();

        const uint32_t bA = sA[buf];
        const uint32_t bB = sB[buf];
        #pragma unroll
        for (int ks = 0; ks < BKH / 16; ++ks) {
            const uint32_t sw = (uint32_t)(((ks*2 + hi) ^ mod7) << 4);
            uint32_t af[2][4], bf[8][2];
            #pragma unroll
            for (int mt = 0; mt < 2; ++mt)
                ldsm_x4(af[mt][0], af[mt][1], af[mt][2], af[mt][3],
                        bA + aoff[mt] + sw);
            #pragma unroll
            for (int j = 0; j < 4; ++j)
                ldsm_x4(bf[2*j][0], bf[2*j+1][0], bf[2*j][1], bf[2*j+1][1],
                        bB + boff[j] + sw);
            #pragma unroll
            for (int mt = 0; mt < 2; ++mt)
                #pragma unroll
                for (int nt = 0; nt < 8; ++nt)
                    mma_f16(acc[mt][nt][0], acc[mt][nt][1],
                            acc[mt][nt][2], acc[mt][nt][3],
                            af[mt][0], af[mt][1], af[mt][2], af[mt][3],
                            bf[nt][0], bf[nt][1]);
        }
        __syncthreads();
    }

    // epilogue: +bias, square-accumulate per row (partial over this n-tile)
    float rowsq[4] = {0.f, 0.f, 0.f, 0.f};
    #pragma unroll
    for (int nt = 0; nt < 8; ++nt) {
        const int cb = n0 + WN + nt*8 + 2*tig;
        const float b0 = __ldg(bias + cb);
        const float b1 = __ldg(bias + cb + 1);
        #pragma unroll
        for (int mt = 0; mt < 2; ++mt) {
            float v0 = acc[mt][nt][0] + b0;
            float v1 = acc[mt][nt][1] + b1;
            float v2 = acc[mt][nt][2] + b0;
            float v3 = acc[mt][nt][3] + b1;
            rowsq[mt*2+0] = fmaf(v0, v0, rowsq[mt*2+0]);
            rowsq[mt*2+0] = fmaf(v1, v1, rowsq[mt*2+0]);
            rowsq[mt*2+1] = fmaf(v2, v2, rowsq[mt*2+1]);
            rowsq[mt*2+1] = fmaf(v3, v3, rowsq[mt*2+1]);
        }
    }
    #pragma unroll
    for (int i = 0; i < 4; ++i) {
        rowsq[i] += __shfl_xor_sync(0xffffffffu, rowsq[i], 1);
        rowsq[i] += __shfl_xor_sync(0xffffffffu, rowsq[i], 2);
    }
    if (tig == 0) {
        #pragma unroll
        for (int mt = 0; mt < 2; ++mt)
            #pragma unroll
            for (int i = 0; i < 2; ++i)
                rowsq_s[WM + mt*16 + i*8 + g][wx] = rowsq[mt*2 + i];
    }
    __syncthreads();
    if (tid < 128)
        g_np[nx][m0 + tid] = rowsq_s[tid][0] + rowsq_s[tid][1];
}

// ---------------------------------------------------------------------------
// Kernel 2: combine rowsq partials -> norm1, then softmax over L -> g_w
// ---------------------------------------------------------------------------
__global__ void k_softmax(float* __restrict__ norm1)
{
    const int b = blockIdx.x;
    const int tid = threadIdx.x;
    __shared__ float red[256];

    for (int l = tid; l < SEQ; l += 256) {
        const int m = b * SEQ + l;
        float s = 0.f;
        #pragma unroll
        for (int j = 0; j < 8; ++j) s += g_np[j][m];
        norm1[m] = sqrtf(s);
    }
    __syncthreads();

    const float* x = norm1 + b * SEQ;
    float m = -1e30f;
    for (int l = tid; l < SEQ; l += 256) m = fmaxf(m, x[l]);
    red[tid] = m; __syncthreads();
    for (int s = 128; s > 0; s >>= 1) {
        if (tid < s) red[tid] = fmaxf(red[tid], red[tid + s]);
        __syncthreads();
    }
    float bm = red[0];
    __syncthreads();

    float sum = 0.0f;
    for (int l = tid; l < SEQ; l += 256) {
        float e = __expf(x[l] - bm);
        g_w[b * SEQ + l] = e;
        sum += e;
    }
    red[tid] = sum; __syncthreads();
    for (int s = 128; s > 0; s >>= 1) {
        if (tid < s) red[tid] += red[tid + s];
        __syncthreads();
    }
    float inv = 1.0f / red[0];
    for (int l = tid; l < SEQ; l += 256) g_w[b * SEQ + l] *= inv;
}

// ---------------------------------------------------------------------------
// Kernel 3: pooled partials from fp16 trg: g_pp[ls][b,k] = sum w[b,l]*trg[b,l,k]
// ---------------------------------------------------------------------------
__global__ void k_pool(void)
{
    const int kc = blockIdx.x;            // 0..2
    const int ls = blockIdx.y;            // 0..7
    const int b  = blockIdx.z;            // 0..31
    const int tid = threadIdx.x;
    const int k0 = kc * 1024 + tid * 4;

    const __half* base = g_trgh + (size_t)b * SEQ * KDIM;
    float4 acc = make_float4(0.f, 0.f, 0.f, 0.f);

    const int l0 = ls * 256;
    #pragma unroll 4
    for (int l = l0; l < l0 + 256; ++l) {
        float wl = g_w[b * SEQ + l];
        uint2 raw = *(const uint2*)(base + (size_t)l * KDIM + k0);
        float2 f0 = __half22float2(*(__half2*)&raw.x);
        float2 f1 = __half22float2(*(__half2*)&raw.y);
        acc.x = fmaf(wl, f0.x, acc.x);
        acc.y = fmaf(wl, f0.y, acc.y);
        acc.z = fmaf(wl, f1.x, acc.z);
        acc.w = fmaf(wl, f1.y, acc.w);
    }
    *(float4*)(&g_pp[ls][b * KDIM + k0]) = acc;
}

// ---------------------------------------------------------------------------
// Kernel 3b: reduce the 8 pooled partials -> g_p
// ---------------------------------------------------------------------------
__global__ __launch_bounds__(256)
void k_red(void)
{
    const int i = blockIdx.x * 256 + threadIdx.x;   // 0 .. BATCH*KDIM-1
    float s = 0.f;
    #pragma unroll
    for (int l = 0; l < 8; ++l) s += g_pp[l][i];
    g_p[i] = s;
}

// ---------------------------------------------------------------------------
// Kernel 4: summ[b,h] = g_p[b,:] . W[h,:] + bias[h]   (fp16 W, fp32 accum)
// ---------------------------------------------------------------------------
__global__ void k_out(const float* __restrict__ bias, float* __restrict__ summ)
{
    const int b = blockIdx.y;
    const int tid = threadIdx.x;
    const int lane = tid & 31;
    const int wid = tid >> 5;

    __shared__ float ps[KDIM];
    for (int k = tid; k < KDIM; k += 256)
        ps[k] = g_p[b * KDIM + k];
    __syncthreads();

    const int h = blockIdx.x * 8 + wid;
    const __half* wr = g_wh + (size_t)h * KDIM;
    float s = 0.0f;
    for (int k = lane * 8; k < KDIM; k += 256) {
        uint4 u = *(const uint4*)(wr + k);
        float2 w0 = __half22float2(*(__half2*)&u.x);
        float2 w1 = __half22float2(*(__half2*)&u.y);
        float2 w2 = __half22float2(*(__half2*)&u.z);
        float2 w3 = __half22float2(*(__half2*)&u.w);
        float4 p0 = *(const float4*)(ps + k);
        float4 p1 = *(const float4*)(ps + k + 4);
        s = fmaf(w0.x, p0.x, s); s = fmaf(w0.y, p0.y, s);
        s = fmaf(w1.x, p0.z, s); s = fmaf(w1.y, p0.w, s);
        s = fmaf(w2.x, p1.x, s); s = fmaf(w2.y, p1.y, s);
        s = fmaf(w3.x, p1.z, s); s = fmaf(w3.y, p1.w, s);
    }
    #pragma unroll
    for (int o = 16; o > 0; o >>= 1) s += __shfl_xor_sync(0xffffffffu, s, o);
    if (lane == 0) summ[b * HID + h] = s + bias[h];
}

// ---------------------------------------------------------------------------
extern "C" void kernel_launch(void* const* d_in, const int* in_sizes, int n_in,
                              void* d_out, int out_size)
{
    const float* trg  = (const float*)d_in[0];
    // d_in[1] = src (unused, n_layers == 0)
    const float* W    = (const float*)d_in[2];
    const float* bias = (const float*)d_in[3];

    float* out   = (float*)d_out;
    float* summ  = out;                   // [32, 1024]
    float* norm1 = out + BATCH * HID;     // [32, 2048]

    __half* trgh; cudaGetSymbolAddress((void**)&trgh, g_trgh);
    __half* wh;   cudaGetSymbolAddress((void**)&wh,   g_wh);

    cudaFuncSetAttribute(k_norm_h, cudaFuncAttributeMaxDynamicSharedMemorySize, SMEM_NORM);

    k_cvt8<<<(HID * KDIM) / (256 * 8), 256>>>(W, wh);
    k_cvt8<<<((size_t)MROWS * KDIM) / (256 * 8), 256>>>(trg, trgh);
    k_norm_h<<<dim3(8, MROWS / 128), 256, SMEM_NORM>>>(bias);
    k_softmax<<<BATCH, 256>>>(norm1);
    k_pool<<<dim3(3, 8, BATCH), 256>>>();
    k_red<<<(BATCH * KDIM) / 256, 256>>>();
    k_out<<<dim3(HID / 8, BATCH), 256>>>(bias, summ);
}

// round 16
// speedup vs baseline: 1.0429x; 1.0070x over previous
#include <cuda_runtime.h>
#include <cuda_fp16.h>
#include <cuda_bf16.h>
#include <math.h>
#include <stdint.h>

// Problem constants
#define BATCH 32
#define SEQ   2048
#define HID   1024
#define KDIM  3072          // 3*HID
#define MROWS (BATCH*SEQ)   // 65536

// Scratch (device globals: allocation-free rule)
__device__ float  g_w[BATCH * SEQ];            // softmax weights
__device__ float  g_pp[8][BATCH * KDIM];       // pooled-trg partials (8 L-splits)
__device__ float  g_p[BATCH * KDIM];           // reduced pooled trg
__device__ float  g_np[8][MROWS];              // per-n-tile rowsq partials
__device__ __half g_trgh[(size_t)MROWS * KDIM];// fp16 trg (403 MB)
__device__ __half g_wh[(size_t)HID * KDIM];    // fp16 W   (6 MB)

// ---------------------------------------------------------------------------
// helpers
// ---------------------------------------------------------------------------
__device__ __forceinline__ uint32_t smem_u32(const void* p) {
    uint32_t a;
    asm("{ .reg .u64 t; cvta.to.shared.u64 t, %1; cvt.u32.u64 %0, t; }"
        : "=r"(a) : "l"(p));
    return a;
}

__device__ __forceinline__ void cp16(uint32_t saddr, const void* gaddr) {
    asm volatile("cp.async.cg.shared.global [%0], [%1], 16;"
                 :: "r"(saddr), "l"(gaddr) : "memory");
}

__device__ __forceinline__ void ldsm_x4(uint32_t& r0, uint32_t& r1,
                                        uint32_t& r2, uint32_t& r3, uint32_t addr) {
    asm volatile("ldmatrix.sync.aligned.m8n8.x4.shared.b16 {%0,%1,%2,%3}, [%4];"
                 : "=r"(r0), "=r"(r1), "=r"(r2), "=r"(r3) : "r"(addr));
}

__device__ __forceinline__ void mma_f16(float& d0, float& d1, float& d2, float& d3,
                                        uint32_t a0, uint32_t a1, uint32_t a2, uint32_t a3,
                                        uint32_t b0, uint32_t b1) {
    asm volatile(
        "mma.sync.aligned.m16n8k16.row.col.f32.f16.f16.f32 "
        "{%0,%1,%2,%3}, {%4,%5,%6,%7}, {%8,%9}, {%0,%1,%2,%3};"
        : "+f"(d0), "+f"(d1), "+f"(d2), "+f"(d3)
        : "r"(a0), "r"(a1), "r"(a2), "r"(a3), "r"(b0), "r"(b1));
}

// ---------------------------------------------------------------------------
// Kernel 0: fp32 -> fp16 conversion, 8 elements/thread
// ---------------------------------------------------------------------------
__global__ __launch_bounds__(256)
void k_cvt8(const float* __restrict__ in, __half* __restrict__ out)
{
    const size_t i = ((size_t)blockIdx.x * 256 + threadIdx.x) * 8;
    float4 v0 = *(const float4*)(in + i);
    float4 v1 = *(const float4*)(in + i + 4);
    __half2 h0 = __floats2half2_rn(v0.x, v0.y);
    __half2 h1 = __floats2half2_rn(v0.z, v0.w);
    __half2 h2 = __floats2half2_rn(v1.x, v1.y);
    __half2 h3 = __floats2half2_rn(v1.z, v1.w);
    uint4 u;
    u.x = *(uint32_t*)&h0; u.y = *(uint32_t*)&h1;
    u.z = *(uint32_t*)&h2; u.w = *(uint32_t*)&h3;
    *(uint4*)(out + i) = u;
}

// ---------------------------------------------------------------------------
// Kernel 1: partial rowsq for one 128x128 output tile, full K.
// 128 threads = 4 warps, warp grid 2(M) x 2(N), warp tile 64x64, 2 CTAs/SM
// -> 256 regs/thread available. Fragment DOUBLE-BUFFERING across k-steps:
// prefetch k-step ks+1's ldmatrix fragments while issuing ks's MMAs, so
// LDSM latency is exposed on only 1 of 4 k-steps per stage (R14 profile
// showed latency-bound: tensor 63%, issue 37%, nothing saturated).
// BK=64 halves, XOR-swizzled smem, double-buffered cp.async.
// ---------------------------------------------------------------------------
#define BKH    64                              // k-halves per stage
#define TILE_B (128 * 128)                     // bytes per tile buffer (16 KB)
#define SMEM_NORM (4 * TILE_B)                 // A0,A1,B0,B1 -> 64 KB
#define NSTG   (KDIM / BKH)                    // 48

__global__ __launch_bounds__(128, 2)
void k_norm_h(const float* __restrict__ bias)
{
    extern __shared__ __align__(128) char smem[];
    const uint32_t sb = smem_u32(smem);
    const uint32_t sA[2] = { sb,            sb + TILE_B };
    const uint32_t sB[2] = { sb + 2*TILE_B, sb + 3*TILE_B };

    __shared__ float rowsq_s[128][2];

    const int tid  = threadIdx.x;
    const int lane = tid & 31;
    const int w    = tid >> 5;                // 0..3
    const int wy   = w >> 1;                  // 0..1  (M)
    const int wx   = w & 1;                   // 0..1  (N)
    const int g    = lane >> 2;               // 0..7
    const int tig  = lane & 3;                // 0..3
    const int WM   = wy * 64;
    const int WN   = wx * 64;
    const int    nx = blockIdx.x;             // n-tile 0..7
    const int    n0 = nx * 128;
    const size_t m0 = (size_t)blockIdx.y * 128;

    // ---- cp.async indexing: 1024 16B-chunks per tile, 8 per thread ----
    const int lc    = tid & 7;
    const int lcol8 = lc * 8;
    int lrow[8], soff[8];
    #pragma unroll
    for (int i = 0; i < 8; ++i) {
        lrow[i] = (tid + i * 128) >> 3;
        soff[i] = lrow[i] * 128 + ((lc ^ (lrow[i] & 7)) << 4);
    }

    const __half* gA = g_trgh + m0 * (size_t)KDIM;
    const __half* gB = g_wh + (size_t)n0 * KDIM;

    // ---- ldmatrix per-lane row bases ----
    const int sub  = ((lane >> 3) & 1) * 8 + (lane & 7);
    const int hi   = (lane >> 4) & 1;
    const int mod7 = lane & 7;
    int aoff[4], boff[4];
    #pragma unroll
    for (int mt = 0; mt < 4; ++mt) aoff[mt] = (WM + mt*16 + sub) * 128;
    #pragma unroll
    for (int j = 0; j < 4; ++j)    boff[j]  = (WN + j*16  + sub) * 128;
    // per-k-step swizzled chunk offsets (constant across stages)
    uint32_t swk[4];
    #pragma unroll
    for (int ks = 0; ks < 4; ++ks)
        swk[ks] = (uint32_t)(((ks*2 + hi) ^ mod7) << 4);

    float acc[4][8][4];
    #pragma unroll
    for (int mt = 0; mt < 4; ++mt)
        #pragma unroll
        for (int nt = 0; nt < 8; ++nt)
            #pragma unroll
            for (int c = 0; c < 4; ++c) acc[mt][nt][c] = 0.f;

    // prologue: stage 0
    #pragma unroll
    for (int i = 0; i < 8; ++i) {
        cp16(sA[0] + soff[i], gA + (size_t)lrow[i] * KDIM + lcol8);
        cp16(sB[0] + soff[i], gB + (size_t)lrow[i] * KDIM + lcol8);
    }
    asm volatile("cp.async.commit_group;" ::: "memory");

    uint32_t af[2][4][4], bf[2][8][2];   // double-buffered fragments

    for (int s = 0; s < NSTG; ++s) {
        const int buf = s & 1;
        if (s + 1 < NSTG) {
            const int nb = buf ^ 1;
            const int k1 = (s + 1) * BKH;
            #pragma unroll
            for (int i = 0; i < 8; ++i) {
                cp16(sA[nb] + soff[i], gA + (size_t)lrow[i] * KDIM + k1 + lcol8);
                cp16(sB[nb] + soff[i], gB + (size_t)lrow[i] * KDIM + k1 + lcol8);
            }
            asm volatile("cp.async.commit_group;" ::: "memory");
            asm volatile("cp.async.wait_group 1;" ::: "memory");
        } else {
            asm volatile("cp.async.wait_group 0;" ::: "memory");
        }
        __syncthreads();

        const uint32_t bA = sA[buf];
        const uint32_t bB = sB[buf];

        // load k-step 0 fragments
        #pragma unroll
        for (int mt = 0; mt < 4; ++mt)
            ldsm_x4(af[0][mt][0], af[0][mt][1], af[0][mt][2], af[0][mt][3],
                    bA + aoff[mt] + swk[0]);
        #pragma unroll
        for (int j = 0; j < 4; ++j)
            ldsm_x4(bf[0][2*j][0], bf[0][2*j+1][0], bf[0][2*j][1], bf[0][2*j+1][1],
                    bB + boff[j] + swk[0]);

        #pragma unroll
        for (int ks = 0; ks < 4; ++ks) {
            const int cur = ks & 1;
            const int nxt = cur ^ 1;
            // prefetch next k-step's fragments (hidden under MMAs below)
            if (ks < 3) {
                #pragma unroll
                for (int mt = 0; mt < 4; ++mt)
                    ldsm_x4(af[nxt][mt][0], af[nxt][mt][1],
                            af[nxt][mt][2], af[nxt][mt][3],
                            bA + aoff[mt] + swk[ks+1]);
                #pragma unroll
                for (int j = 0; j < 4; ++j)
                    ldsm_x4(bf[nxt][2*j][0], bf[nxt][2*j+1][0],
                            bf[nxt][2*j][1], bf[nxt][2*j+1][1],
                            bB + boff[j] + swk[ks+1]);
            }
            #pragma unroll
            for (int mt = 0; mt < 4; ++mt)
                #pragma unroll
                for (int nt = 0; nt < 8; ++nt)
                    mma_f16(acc[mt][nt][0], acc[mt][nt][1],
                            acc[mt][nt][2], acc[mt][nt][3],
                            af[cur][mt][0], af[cur][mt][1],
                            af[cur][mt][2], af[cur][mt][3],
                            bf[cur][nt][0], bf[cur][nt][1]);
        }
        __syncthreads();
    }

    // epilogue: +bias, square-accumulate per row (partial over this n-tile)
    float rowsq[8];
    #pragma unroll
    for (int i = 0; i < 8; ++i) rowsq[i] = 0.f;
    #pragma unroll
    for (int nt = 0; nt < 8; ++nt) {
        const int cb = n0 + WN + nt*8 + 2*tig;
        const float b0 = __ldg(bias + cb);
        const float b1 = __ldg(bias + cb + 1);
        #pragma unroll
        for (int mt = 0; mt < 4; ++mt) {
            float v0 = acc[mt][nt][0] + b0;
            float v1 = acc[mt][nt][1] + b1;
            float v2 = acc[mt][nt][2] + b0;
            float v3 = acc[mt][nt][3] + b1;
            rowsq[mt*2+0] = fmaf(v0, v0, rowsq[mt*2+0]);
            rowsq[mt*2+0] = fmaf(v1, v1, rowsq[mt*2+0]);
            rowsq[mt*2+1] = fmaf(v2, v2, rowsq[mt*2+1]);
            rowsq[mt*2+1] = fmaf(v3, v3, rowsq[mt*2+1]);
        }
    }
    #pragma unroll
    for (int i = 0; i < 8; ++i) {
        rowsq[i] += __shfl_xor_sync(0xffffffffu, rowsq[i], 1);
        rowsq[i] += __shfl_xor_sync(0xffffffffu, rowsq[i], 2);
    }
    if (tig == 0) {
        #pragma unroll
        for (int mt = 0; mt < 4; ++mt)
            #pragma unroll
            for (int i = 0; i < 2; ++i)
                rowsq_s[WM + mt*16 + i*8 + g][wx] = rowsq[mt*2 + i];
    }
    __syncthreads();
    // 128 threads: one per output row
    g_np[nx][m0 + tid] = rowsq_s[tid][0] + rowsq_s[tid][1];
}

// ---------------------------------------------------------------------------
// Kernel 2: combine rowsq partials -> norm1, then softmax over L -> g_w
// ---------------------------------------------------------------------------
__global__ void k_softmax(float* __restrict__ norm1)
{
    const int b = blockIdx.x;
    const int tid = threadIdx.x;
    __shared__ float red[256];

    for (int l = tid; l < SEQ; l += 256) {
        const int m = b * SEQ + l;
        float s = 0.f;
        #pragma unroll
        for (int j = 0; j < 8; ++j) s += g_np[j][m];
        norm1[m] = sqrtf(s);
    }
    __syncthreads();

    const float* x = norm1 + b * SEQ;
    float m = -1e30f;
    for (int l = tid; l < SEQ; l += 256) m = fmaxf(m, x[l]);
    red[tid] = m; __syncthreads();
    for (int s = 128; s > 0; s >>= 1) {
        if (tid < s) red[tid] = fmaxf(red[tid], red[tid + s]);
        __syncthreads();
    }
    float bm = red[0];
    __syncthreads();

    float sum = 0.0f;
    for (int l = tid; l < SEQ; l += 256) {
        float e = __expf(x[l] - bm);
        g_w[b * SEQ + l] = e;
        sum += e;
    }
    red[tid] = sum; __syncthreads();
    for (int s = 128; s > 0; s >>= 1) {
        if (tid < s) red[tid] += red[tid + s];
        __syncthreads();
    }
    float inv = 1.0f / red[0];
    for (int l = tid; l < SEQ; l += 256) g_w[b * SEQ + l] *= inv;
}

// ---------------------------------------------------------------------------
// Kernel 3: pooled partials from fp16 trg: g_pp[ls][b,k] = sum w[b,l]*trg[b,l,k]
// ---------------------------------------------------------------------------
__global__ void k_pool(void)
{
    const int kc = blockIdx.x;            // 0..2
    const int ls = blockIdx.y;            // 0..7
    const int b  = blockIdx.z;            // 0..31
    const int tid = threadIdx.x;
    const int k0 = kc * 1024 + tid * 4;

    const __half* base = g_trgh + (size_t)b * SEQ * KDIM;
    float4 acc = make_float4(0.f, 0.f, 0.f, 0.f);

    const int l0 = ls * 256;
    #pragma unroll 4
    for (int l = l0; l < l0 + 256; ++l) {
        float wl = g_w[b * SEQ + l];
        uint2 raw = *(const uint2*)(base + (size_t)l * KDIM + k0);
        float2 f0 = __half22float2(*(__half2*)&raw.x);
        float2 f1 = __half22float2(*(__half2*)&raw.y);
        acc.x = fmaf(wl, f0.x, acc.x);
        acc.y = fmaf(wl, f0.y, acc.y);
        acc.z = fmaf(wl, f1.x, acc.z);
        acc.w = fmaf(wl, f1.y, acc.w);
    }
    *(float4*)(&g_pp[ls][b * KDIM + k0]) = acc;
}

// ---------------------------------------------------------------------------
// Kernel 3b: reduce the 8 pooled partials -> g_p
// ---------------------------------------------------------------------------
__global__ __launch_bounds__(256)
void k_red(void)
{
    const int i = blockIdx.x * 256 + threadIdx.x;   // 0 .. BATCH*KDIM-1
    float s = 0.f;
    #pragma unroll
    for (int l = 0; l < 8; ++l) s += g_pp[l][i];
    g_p[i] = s;
}

// ---------------------------------------------------------------------------
// Kernel 4: summ[b,h] = g_p[b,:] . W[h,:] + bias[h]   (fp16 W, fp32 accum)
// ---------------------------------------------------------------------------
__global__ void k_out(const float* __restrict__ bias, float* __restrict__ summ)
{
    const int b = blockIdx.y;
    const int tid = threadIdx.x;
    const int lane = tid & 31;
    const int wid = tid >> 5;

    __shared__ float ps[KDIM];
    for (int k = tid; k < KDIM; k += 256)
        ps[k] = g_p[b * KDIM + k];
    __syncthreads();

    const int h = blockIdx.x * 8 + wid;
    const __half* wr = g_wh + (size_t)h * KDIM;
    float s = 0.0f;
    for (int k = lane * 8; k < KDIM; k += 256) {
        uint4 u = *(const uint4*)(wr + k);
        float2 w0 = __half22float2(*(__half2*)&u.x);
        float2 w1 = __half22float2(*(__half2*)&u.y);
        float2 w2 = __half22float2(*(__half2*)&u.z);
        float2 w3 = __half22float2(*(__half2*)&u.w);
        float4 p0 = *(const float4*)(ps + k);
        float4 p1 = *(const float4*)(ps + k + 4);
        s = fmaf(w0.x, p0.x, s); s = fmaf(w0.y, p0.y, s);
        s = fmaf(w1.x, p0.z, s); s = fmaf(w1.y, p0.w, s);
        s = fmaf(w2.x, p1.x, s); s = fmaf(w2.y, p1.y, s);
        s = fmaf(w3.x, p1.z, s); s = fmaf(w3.y, p1.w, s);
    }
    #pragma unroll
    for (int o = 16; o > 0; o >>= 1) s += __shfl_xor_sync(0xffffffffu, s, o);
    if (lane == 0) summ[b * HID + h] = s + bias[h];
}

// ---------------------------------------------------------------------------
extern "C" void kernel_launch(void* const* d_in, const int* in_sizes, int n_in,
                              void* d_out, int out_size)
{
    const float* trg  = (const float*)d_in[0];
    // d_in[1] = src (unused, n_layers == 0)
    const float* W    = (const float*)d_in[2];
    const float* bias = (const float*)d_in[3];

    float* out   = (float*)d_out;
    float* summ  = out;                   // [32, 1024]
    float* norm1 = out + BATCH * HID;     // [32, 2048]

    __half* trgh; cudaGetSymbolAddress((void**)&trgh, g_trgh);
    __half* wh;   cudaGetSymbolAddress((void**)&wh,   g_wh);

    cudaFuncSetAttribute(k_norm_h, cudaFuncAttributeMaxDynamicSharedMemorySize, SMEM_NORM);

    k_cvt8<<<(HID * KDIM) / (256 * 8), 256>>>(W, wh);
    k_cvt8<<<((size_t)MROWS * KDIM) / (256 * 8), 256>>>(trg, trgh);
    k_norm_h<<<dim3(8, MROWS / 128), 128, SMEM_NORM>>>(bias);
    k_softmax<<<BATCH, 256>>>(norm1);
    k_pool<<<dim3(3, 8, BATCH), 256>>>();
    k_red<<<(BATCH * KDIM) / 256, 256>>>();
    k_out<<<dim3(HID / 8, BATCH), 256>>>(bias, summ);
}